// round 6
// baseline (speedup 1.0000x reference)
#include <cuda_runtime.h>

typedef unsigned long long u64;

#define TSEQ 64
#define NB 2048
#define MAX_STEPS 16
#define FULLM 0xffffffffu

// ---------------- packed fp32x2 + MUFU helpers ----------------
__device__ __forceinline__ u64 ffma2(u64 a, u64 b, u64 c) {
    u64 d; asm("fma.rn.f32x2 %0, %1, %2, %3;" : "=l"(d) : "l"(a), "l"(b), "l"(c)); return d;
}
__device__ __forceinline__ u64 fmul2(u64 a, u64 b) {
    u64 d; asm("mul.rn.f32x2 %0, %1, %2;" : "=l"(d) : "l"(a), "l"(b)); return d;
}
__device__ __forceinline__ u64 fadd2(u64 a, u64 b) {
    u64 d; asm("add.rn.f32x2 %0, %1, %2;" : "=l"(d) : "l"(a), "l"(b)); return d;
}
__device__ __forceinline__ float2 unpk2(u64 a) {
    float lo, hi; asm("mov.b64 {%0, %1}, %2;" : "=f"(lo), "=f"(hi) : "l"(a));
    return make_float2(lo, hi);
}
__device__ __forceinline__ u64 pk2(float lo, float hi) {
    u64 d; asm("mov.b64 %0, {%1, %2};" : "=l"(d) : "f"(lo), "f"(hi)); return d;
}
__device__ __forceinline__ float ex2a(float x){ float r; asm("ex2.approx.f32 %0, %1;" : "=f"(r) : "f"(x)); return r; }
__device__ __forceinline__ float rcpa(float x){ float r; asm("rcp.approx.f32 %0, %1;" : "=f"(r) : "f"(x)); return r; }
__device__ __forceinline__ float lg2a(float x){ float r; asm("lg2.approx.f32 %0, %1;" : "=f"(r) : "f"(x)); return r; }

#define TWO_LOG2E 2.885390081777927f

// tanh(z + b) with prescaled bias bs = TWO_LOG2E*b
__device__ __forceinline__ float tanh_pre(float z, float bs){
    float e = ex2a(fmaf(z, TWO_LOG2E, bs));
    return fmaf(-2.0f, rcpa(e + 1.0f), 1.0f);
}
__device__ __forceinline__ float fast_tanh(float x){
    float e = ex2a(x * TWO_LOG2E);
    return fmaf(-2.0f, rcpa(e + 1.0f), 1.0f);
}
__device__ __forceinline__ float fast_sigmoid(float x){
    float e = ex2a(x * -1.4426950408889634f);
    return rcpa(e + 1.0f);
}

// dot of 16-float smem vector (16B aligned, broadcast-read) vs packed weight row
__device__ __forceinline__ float dot16s(const float* __restrict__ src, const u64* w){
    const ulonglong2* v = (const ulonglong2*)src;
    ulonglong2 a0 = v[0], a1 = v[1], a2 = v[2], a3 = v[3];
    u64 s0 = fmul2(a0.x, w[0]);
    u64 s1 = fmul2(a0.y, w[1]);
    u64 s2 = fmul2(a1.x, w[2]);
    u64 s3 = fmul2(a1.y, w[3]);
    s0 = ffma2(a2.x, w[4], s0);
    s1 = ffma2(a2.y, w[5], s1);
    s2 = ffma2(a3.x, w[6], s2);
    s3 = ffma2(a3.y, w[7], s3);
    u64 t0 = fadd2(s0, s1);
    u64 t1 = fadd2(s2, s3);
    u64 t2 = fadd2(t0, t1);
    float2 f = unpk2(t2);
    return f.x + f.y;
}

// dot of two packed register rows
__device__ __forceinline__ float dot16r(const u64* v, const u64* w){
    u64 s0 = fmul2(v[0], w[0]);
    u64 s1 = fmul2(v[1], w[1]);
    u64 s2 = fmul2(v[2], w[2]);
    u64 s3 = fmul2(v[3], w[3]);
    s0 = ffma2(v[4], w[4], s0);
    s1 = ffma2(v[5], w[5], s1);
    s2 = ffma2(v[6], w[6], s2);
    s3 = ffma2(v[7], w[7], s3);
    u64 t0 = fadd2(s0, s1);
    u64 t1 = fadd2(s2, s3);
    u64 t2 = fadd2(t0, t1);
    float2 f = unpk2(t2);
    return f.x + f.y;
}

// sum of 16 floats from smem (broadcast-read)
__device__ __forceinline__ float sum16s(const float* __restrict__ src){
    const ulonglong2* v = (const ulonglong2*)src;
    ulonglong2 a0 = v[0], a1 = v[1], a2 = v[2], a3 = v[3];
    u64 t0 = fadd2(a0.x, a0.y);
    u64 t1 = fadd2(a1.x, a1.y);
    u64 t2 = fadd2(a2.x, a2.y);
    u64 t3 = fadd2(a3.x, a3.y);
    u64 t4 = fadd2(t0, t1);
    u64 t5 = fadd2(t2, t3);
    u64 t6 = fadd2(t4, t5);
    float2 f = unpk2(t6);
    return f.x + f.y;
}

__device__ __forceinline__ void load_row16(const float* __restrict__ base, u64* wp){
    const float4* p = (const float4*)base;
#pragma unroll
    for (int k = 0; k < 4; ++k) {
        float4 f = p[k];
        wp[2*k]   = pk2(f.x, f.y);
        wp[2*k+1] = pk2(f.z, f.w);
    }
}

__global__ void __launch_bounds__(32) ode_rnn_kernel(
    const float* __restrict__ x_seq,
    const float* __restrict__ w1, const float* __restrict__ b1,
    const float* __restrict__ w2, const float* __restrict__ b2,
    const float* __restrict__ w3, const float* __restrict__ b3,
    const float* __restrict__ gwih, const float* __restrict__ gwhh,
    const float* __restrict__ gb,  const float* __restrict__ gbn,
    const float* __restrict__ pw,  const float* __restrict__ pb,
    float* __restrict__ out)
{
    const int lane = threadIdx.x;
    const int l = lane & 15;          // hidden component
    const int s = lane >> 4;          // sample within warp (0/1)
    const int b = blockIdx.x * 2 + s;

    // ping-pong broadcast buffers per sample; 48-float sample stride keeps the
    // two samples' active buffers in disjoint bank halves for both parities.
    __shared__ __align__(16) float sbuf[2*48];
    __shared__ __align__(16) float w3s[16*16];   // staging for w1w3 precompute
    float* cur = sbuf + s * 48;
    float* alt = cur + 16;

    // register-resident weights (rows owned by this lane)
    u64 w1p[8], w2p[8], w3p[8], whr[8], whz[8], whn[8];
    load_row16(w1 + l*16, w1p);
    load_row16(w2 + l*16, w2p);
    load_row16(w3 + l*16, w3p);
    load_row16(gwhh + l*16,      whr);
    load_row16(gwhh + (16+l)*16, whz);
    load_row16(gwhh + (32+l)*16, whn);
    const float b1s = b1[l] * TWO_LOG2E;
    const float b2s = b2[l] * TWO_LOG2E;
    const float b3v = b3[l];
    const float wr0 = gwih[l*2],      wr1 = gwih[l*2+1];
    const float wz0 = gwih[(16+l)*2], wz1 = gwih[(16+l)*2+1];
    const float wn0 = gwih[(32+l)*2], wn1 = gwih[(32+l)*2+1];
    const float gbr = gb[l], gbz = gb[16+l], gbnn = gb[32+l];
    const float bnv = gbn[l];
    const float pwv = pw[l];
    const float pbv = pb[0];

    // ---- one-time precompute: w13 = w1 @ w3 (row l), w1b3 = (w1 @ b3)[l] ----
    if (s == 0) {
        float4* dst = (float4*)(w3s + l*16);
        const float4* srcp = (const float4*)(w3 + l*16);
        dst[0] = srcp[0]; dst[1] = srcp[1]; dst[2] = srcp[2]; dst[3] = srcp[3];
    }
    __syncwarp();
    u64 w13p[8];
#pragma unroll
    for (int i = 0; i < 8; ++i) w13p[i] = 0ull;     // packed (0,0)
#pragma unroll
    for (int j = 0; j < 16; ++j) {
        float2 pr = unpk2(w1p[j >> 1]);
        float c = (j & 1) ? pr.y : pr.x;
        u64 cc = pk2(c, c);
        const ulonglong2* r = (const ulonglong2*)(w3s + j*16);
        ulonglong2 r0 = r[0], r1 = r[1], r2 = r[2], r3 = r[3];
        w13p[0] = ffma2(cc, r0.x, w13p[0]);
        w13p[1] = ffma2(cc, r0.y, w13p[1]);
        w13p[2] = ffma2(cc, r1.x, w13p[2]);
        w13p[3] = ffma2(cc, r1.y, w13p[3]);
        w13p[4] = ffma2(cc, r2.x, w13p[4]);
        w13p[5] = ffma2(cc, r2.y, w13p[5]);
        w13p[6] = ffma2(cc, r3.x, w13p[6]);
        w13p[7] = ffma2(cc, r3.y, w13p[7]);
    }
    float w1b3v;
    {
        u64 b3q[8];
        load_row16(b3, b3q);
        w1b3v = dot16r(b3q, w1p);
    }
    __syncwarp();   // all lanes done with w3s before sbuf traffic begins

#define SWAPBUF { float* _t = cur; cur = alt; alt = _t; }
    // Eval f at arg with z1 = (w1 @ arg) supplied per-lane.  Produces
    // k = f(arg)[l] and u = (w1 @ f(arg))[l] via the precomputed w13.
#define F_EVAL2(z1, kout, uout) do {                                        \
        float _h1 = tanh_pre((z1), b1s);                                    \
        cur[l] = _h1; __syncwarp();                                         \
        float _d2 = dot16s(cur, w2p); SWAPBUF;                              \
        float _h2 = tanh_pre(_d2, b2s);                                     \
        cur[l] = _h2; __syncwarp();                                         \
        kout = dot16s(cur, w3p) + b3v;                                      \
        uout = dot16s(cur, w13p) + w1b3v; SWAPBUF;                          \
    } while (0)

    float y = 0.0f, w1y = 0.0f;       // h0 = 0 -> w1@h0 = 0 exactly
    const float* xb = x_seq + (size_t)b * (TSEQ*2);

#pragma unroll 1
    for (int ts = 0; ts < TSEQ; ++ts) {
        const float x0 = xb[ts*2 + 0];
        const float x1 = xb[ts*2 + 1];
        const float ir  = fmaf(x0, wr0, fmaf(x1, wr1, gbr));
        const float iz  = fmaf(x0, wz0, fmaf(x1, wz1, gbz));
        const float inn = fmaf(x0, wn0, fmaf(x1, wn1, gbnn));

        // ---- adaptive Tsit5, t: 0 -> 1 ----
        float t = 0.0f, dt = 1.0f;
        float k1, u1;
        F_EVAL2(w1y, k1, u1);         // FSAL seed (z1 = w1@y)
#pragma unroll 1
        for (int it = 0; it < MAX_STEPS; ++it) {
            float dt_c = fminf(dt, 1.0f - t);

            float a, k2,u2, k3,u3, k4,u4, k5,u5, k6,u6, k7,u7;
            a = 0.161f * u1;
            F_EVAL2(fmaf(dt_c, a, w1y), k2, u2);
            a = fmaf(0.335480655492357f, u2, -0.008480655492356989f * u1);
            F_EVAL2(fmaf(dt_c, a, w1y), k3, u3);
            a = 2.8971530571054935f * u1;
            a = fmaf(-6.359448489975075f, u2, a);
            a = fmaf(4.3622954328695815f, u3, a);
            F_EVAL2(fmaf(dt_c, a, w1y), k4, u4);
            a = 5.325864828439257f * u1;
            a = fmaf(-11.748883564062828f, u2, a);
            a = fmaf(7.4955393428898365f, u3, a);
            a = fmaf(-0.09249506636175525f, u4, a);
            F_EVAL2(fmaf(dt_c, a, w1y), k5, u5);
            a = 5.86145544294642f * u1;
            a = fmaf(-12.92096931784711f, u2, a);
            a = fmaf(8.159367898576159f, u3, a);
            a = fmaf(-0.071584973281401f, u4, a);
            a = fmaf(-0.028269050394068383f, u5, a);
            F_EVAL2(fmaf(dt_c, a, w1y), k6, u6);

            a = 0.09646076681806523f * k1;
            a = fmaf(0.01f, k2, a);
            a = fmaf(0.4798896504144996f, k3, a);
            a = fmaf(1.379008574103742f, k4, a);
            a = fmaf(-3.290069515436081f, k5, a);
            a = fmaf(2.324710524099774f, k6, a);
            float y_new = fmaf(dt_c, a, y);
            a = 0.09646076681806523f * u1;
            a = fmaf(0.01f, u2, a);
            a = fmaf(0.4798896504144996f, u3, a);
            a = fmaf(1.379008574103742f, u4, a);
            a = fmaf(-3.290069515436081f, u5, a);
            a = fmaf(2.324710524099774f, u6, a);
            float w1y_new = fmaf(dt_c, a, w1y);
            F_EVAL2(w1y_new, k7, u7);

            a = -0.001780011052225777f * k1;
            a = fmaf(-0.0008164344596567469f, k2, a);
            a = fmaf(0.007880878010261995f, k3, a);
            a = fmaf(-0.1447110071732629f, k4, a);
            a = fmaf(0.5823571654525552f, k5, a);
            a = fmaf(-0.45808210592918697f, k6, a);
            a = fmaf(0.015151515151515152f, k7, a);
            float err = dt_c * a;
            float scale = fmaf(0.01f, fmaxf(fabsf(y), fabsf(y_new)), 0.0001f);
            float q = err * rcpa(scale);
            float e = q * q;
            // mean over 16 lanes via smem broadcast + packed add tree
            cur[l] = e; __syncwarp();
            float esum = sum16s(cur); SWAPBUF;
            float err2 = fmaxf(esum * 0.0625f, 1e-16f);

            bool accept = (err2 <= 1.0f);
            if (accept) { y = y_new; w1y = w1y_new; t = t + dt_c; k1 = k7; u1 = u7; }
            float factor = fminf(fmaxf(0.9f * ex2a(-0.1f * lg2a(err2)), 0.2f), 10.0f);
            dt = dt_c * factor;

            // exact freeze: frozen iterations are bit-exact identities
            if (__all_sync(FULLM, t >= 1.0f)) break;
        }

        // ---- GRU update with x_t ----
        cur[l] = y; __syncwarp();
        float hr = dot16s(cur, whr);
        float hz = dot16s(cur, whz);
        float hn = dot16s(cur, whn);
        SWAPBUF;
        float r = fast_sigmoid(ir + hr);
        float z = fast_sigmoid(iz + hz);
        float n = fast_tanh(fmaf(r, hn + bnv, inn));
        y = n + z * (y - n);

        // refresh w1y = w1 @ y for the next timestep's ODE
        cur[l] = y; __syncwarp();
        w1y = dot16s(cur, w1p);
        SWAPBUF;
    }

    // ---- prediction head ----
    float v = y * pwv;
    v += __shfl_xor_sync(FULLM, v, 8);
    v += __shfl_xor_sync(FULLM, v, 4);
    v += __shfl_xor_sync(FULLM, v, 2);
    v += __shfl_xor_sync(FULLM, v, 1);
    if (l == 0) out[b] = v + pbv;
#undef F_EVAL2
#undef SWAPBUF
}

extern "C" void kernel_launch(void* const* d_in, const int* in_sizes, int n_in,
                              void* d_out, int out_size) {
    (void)in_sizes; (void)n_in; (void)out_size;
    ode_rnn_kernel<<<NB/2, 32>>>(
        (const float*)d_in[0],
        (const float*)d_in[1],  (const float*)d_in[2],
        (const float*)d_in[3],  (const float*)d_in[4],
        (const float*)d_in[5],  (const float*)d_in[6],
        (const float*)d_in[7],  (const float*)d_in[8],
        (const float*)d_in[9],  (const float*)d_in[10],
        (const float*)d_in[11], (const float*)d_in[12],
        (float*)d_out);
}